// round 15
// baseline (speedup 1.0000x reference)
#include <cuda_runtime.h>

typedef unsigned long long u64;

#define BB 32
#define NN 256
#define NF 16
#define NL 3
#define NODES (BB*NN)
#define WPB 4   // warps (dst nodes) per block

// ping-pong state; precomputed node terms double-buffered by layer parity
__device__ float4 g_x[2][NODES];
__device__ float  g_h[2][NODES*NF];
__device__ u64    g_A2[2][NODES*(NF/2)];    // packed pairs: h_i @ We1[0:NF]
__device__ u64    g_Bjb2[2][NODES*(NF/2)];  // packed pairs: h_j @ We1[NF:2NF] + be1
__device__ float  g_hWh[2][NODES*NF];       // h_j @ Wh1[0:NF] + bh1
__device__ float  g_hv[2][NODES];           // h_j @ W_v

// ---- packed fp32x2 helpers (sm_103a FFMA2 path, PTX-only) ----
__device__ __forceinline__ u64 pk(float lo, float hi) {
    u64 r; asm("mov.b64 %0, {%1,%2};" : "=l"(r) : "f"(lo), "f"(hi)); return r;
}
__device__ __forceinline__ float2 upk(u64 v) {
    float2 r; asm("mov.b64 {%0,%1}, %2;" : "=f"(r.x), "=f"(r.y) : "l"(v)); return r;
}
__device__ __forceinline__ void f2fma_acc(u64& d, u64 a, u64 b) {
    asm("fma.rn.f32x2 %0, %1, %2, %0;" : "+l"(d) : "l"(a), "l"(b));
}
__device__ __forceinline__ u64 f2fma(u64 a, u64 b, u64 c) {
    u64 d; asm("fma.rn.f32x2 %0, %1, %2, %3;" : "=l"(d) : "l"(a), "l"(b), "l"(c)); return d;
}
__device__ __forceinline__ u64 f2add(u64 a, u64 b) {
    u64 d; asm("add.rn.f32x2 %0, %1, %2;" : "=l"(d) : "l"(a), "l"(b)); return d;
}

// init: node features h from charges, plus layer-0 node-side precompute (buffer 0)
__global__ void init_kernel(const float* __restrict__ xs,
                            const float* __restrict__ charges,
                            const float* __restrict__ W_in,
                            const float* __restrict__ b_in,
                            const float* __restrict__ W_v,
                            const float* __restrict__ We1,
                            const float* __restrict__ be1,
                            const float* __restrict__ Wh1,
                            const float* __restrict__ bh1) {
    int gid = blockIdx.x * blockDim.x + threadIdx.x;
    int node = gid >> 4;
    int k = gid & 15;
    if (node >= NODES) return;
    float c = charges[node];
    float h[NF];
    #pragma unroll
    for (int f = 0; f < NF; f++) {
        float v = fmaf(c, W_in[f], b_in[f]);
        h[f] = v > 0.f ? v : 0.f;
    }
    g_h[0][node*NF + k] = h[k];
    float a = 0.f, bb = 0.f, hw = 0.f;
    #pragma unroll
    for (int f = 0; f < NF; f++) {
        a  = fmaf(h[f], We1[f*NF + k],      a);
        bb = fmaf(h[f], We1[(NF+f)*NF + k], bb);
        hw = fmaf(h[f], Wh1[f*NF + k],      hw);
    }
    ((float*)g_A2[0])[node*NF + k]   = a;
    ((float*)g_Bjb2[0])[node*NF + k] = bb + be1[k];
    g_hWh[0][node*NF + k] = hw + bh1[k];
    if (k == 0) {
        float hv = 0.f;
        #pragma unroll
        for (int f = 0; f < NF; f++) hv = fmaf(h[f], W_v[f], hv);
        g_hv[0][node] = hv;
        float4 x;
        x.x = xs[node*3 + 0]; x.y = xs[node*3 + 1]; x.z = xs[node*3 + 2]; x.w = 0.f;
        g_x[0][node] = x;
    }
}

// one We2 row pass applied to TWO edges: weights loaded once, two FFMA2 streams
#define WE2_ROW2(TA, TB, F)                                          \
    do {                                                             \
        ulonglong2 wa = sWe2v[(F)*4 + 0];                            \
        ulonglong2 wb = sWe2v[(F)*4 + 1];                            \
        ulonglong2 wc = sWe2v[(F)*4 + 2];                            \
        ulonglong2 wd = sWe2v[(F)*4 + 3];                            \
        f2fma_acc(m2a[0], TA, wa.x); f2fma_acc(m2b[0], TB, wa.x);    \
        f2fma_acc(m2a[1], TA, wa.y); f2fma_acc(m2b[1], TB, wa.y);    \
        f2fma_acc(m2a[2], TA, wb.x); f2fma_acc(m2b[2], TB, wb.x);    \
        f2fma_acc(m2a[3], TA, wb.y); f2fma_acc(m2b[3], TB, wb.y);    \
        f2fma_acc(m2a[4], TA, wc.x); f2fma_acc(m2b[4], TB, wc.x);    \
        f2fma_acc(m2a[5], TA, wc.y); f2fma_acc(m2b[5], TB, wc.y);    \
        f2fma_acc(m2a[6], TA, wd.x); f2fma_acc(m2b[6], TB, wd.x);    \
        f2fma_acc(m2a[7], TA, wd.y); f2fma_acc(m2b[7], TB, wd.y);    \
    } while (0)

// min_blocks 6: caps regs at ~85 -> 6 blocks/SM (24 warps, 6/SMSP).
// R14 proved the load batching is elastic (96 regs, zero spills at cap 102);
// accumulator floor is 48 regs, so 85 leaves ~4-deep LDS batches spill-free.
__global__ void __launch_bounds__(WPB*32, 6)
edge_kernel(int l, int cur, int nxt, int last,
            const float* __restrict__ We1,
            const float* __restrict__ be1,
            const float* __restrict__ We2,
            const float* __restrict__ be2,
            const float* __restrict__ Wx,
            const float* __restrict__ Wh1,
            const float* __restrict__ bh1,
            const float* __restrict__ W_v,
            const float* __restrict__ vs,
            float* __restrict__ out) {
    __shared__ ulonglong2 sA2[4*NN];      // [p*NN + i] = (A pairs 2p, 2p+1); reused in epilogue
    __shared__ float4     sX[NN];
    __shared__ ulonglong2 sWe2v[NF*4];    // row f at [f*4..f*4+3]
    __shared__ ulonglong2 sBe2[4];        // be2[l] as 8 packed pairs
    __shared__ ulonglong2 sWxv[4];        // Wx[l]  as 8 packed pairs
    __shared__ ulonglong2 sWr2[4];        // We1 r2-row as 8 packed pairs
    __shared__ ulonglong2 sBjbW[WPB*4];   // per-warp Bjb pairs
    __shared__ float      sWh1b[NF*NF];   // Wh1 m_agg half [f][k]
    __shared__ float      sHn[WPB*NF];

    int tid  = threadIdx.x;
    int lane = tid & 31;
    int warp = tid >> 5;
    int b     = blockIdx.x >> 6;          // NN/WPB = 64 blocks per batch
    int jbase = (blockIdx.x & 63) * WPB;
    int nbase = b * NN;

    int pc = l & 1;        // precompute buffer for this layer
    int pn = pc ^ 1;       // precompute buffer for next layer

    int j = jbase + warp;
    int node = nbase + j;

    // cooperative tile loads
    for (int idx = tid; idx < NN*4; idx += WPB*32) {
        int i = idx >> 2, p = idx & 3;
        sA2[p*NN + i] = ((const ulonglong2*)g_A2[pc])[(nbase + i)*4 + p];
    }
    for (int i = tid; i < NN; i += WPB*32) sX[i] = g_x[cur][nbase + i];
    if (tid < NF*4) sWe2v[tid] = ((const ulonglong2*)We2)[l*(NF*NF/4) + tid];
    if (tid >= 64 && tid < 68) sBe2[tid-64] = ((const ulonglong2*)be2)[l*4 + (tid-64)];
    if (tid >= 68 && tid < 72) sWxv[tid-68] = ((const ulonglong2*)Wx)[l*4 + (tid-68)];
    if (tid >= 72 && tid < 76)
        sWr2[tid-72] = ((const ulonglong2*)We1)[(l*(2*NF+1)*NF + 2*NF*NF)/4 + (tid-72)];
    if (lane < 4) sBjbW[warp*4 + lane] = ((const ulonglong2*)g_Bjb2[pc])[node*4 + lane];
    for (int idx = tid; idx < NF*NF; idx += WPB*32) {
        int f = idx >> 4, k = idx & 15;
        sWh1b[idx] = Wh1[l*(2*NF)*NF + (NF + f)*NF + k];
    }
    __syncthreads();

    float4 xj = sX[j];

    u64 magg2[8];
    #pragma unroll
    for (int q = 0; q < 8; q++) magg2[q] = 0ull;
    float ax = 0.f, ay = 0.f, az = 0.f;

    // Two edges per lane per iteration: i1 = it*64+lane, i2 = i1+32.
    // Weights loaded once per chunk feed BOTH m2a and m2b streams.
    #pragma unroll 1
    for (int it = 0; it < NN/64; it++) {
        int i1 = it*64 + lane;
        int i2 = i1 + 32;
        float4 xi1 = sX[i1];
        float4 xi2 = sX[i2];
        float dx1 = xj.x - xi1.x, dy1 = xj.y - xi1.y, dz1 = xj.z - xi1.z;
        float dx2 = xj.x - xi2.x, dy2 = xj.y - xi2.y, dz2 = xj.z - xi2.z;
        float r2a = fmaf(dx1, dx1, fmaf(dy1, dy1, dz1*dz1));
        float r2b = fmaf(dx2, dx2, fmaf(dy2, dy2, dz2*dz2));
        u64 r22a = pk(r2a, r2a);
        u64 r22b = pk(r2b, r2b);

        u64 m2a[8], m2b[8];
        {
            ulonglong2 b0 = sBe2[0], b1 = sBe2[1], b2 = sBe2[2], b3 = sBe2[3];
            m2a[0] = b0.x; m2a[1] = b0.y; m2a[2] = b1.x; m2a[3] = b1.y;
            m2a[4] = b2.x; m2a[5] = b2.y; m2a[6] = b3.x; m2a[7] = b3.y;
            m2b[0] = b0.x; m2b[1] = b0.y; m2b[2] = b1.x; m2b[3] = b1.y;
            m2b[4] = b2.x; m2b[5] = b2.y; m2b[6] = b3.x; m2b[7] = b3.y;
        }

        // unroll 1: bounds the LDS batch per chunk (spill guard, see R10->R11)
        #pragma unroll 1
        for (int p = 0; p < 4; p++) {
            ulonglong2 a2a = sA2[p*NN + i1];
            ulonglong2 a2b = sA2[p*NN + i2];
            ulonglong2 bj  = sBjbW[warp*4 + p];
            ulonglong2 wr  = sWr2[p];
            float2 ta0 = upk(f2fma(r22a, wr.x, f2add(a2a.x, bj.x)));
            float2 ta1 = upk(f2fma(r22a, wr.y, f2add(a2a.y, bj.y)));
            float2 tb0 = upk(f2fma(r22b, wr.x, f2add(a2b.x, bj.x)));
            float2 tb1 = upk(f2fma(r22b, wr.y, f2add(a2b.y, bj.y)));
            u64 tA, tB;
            tA = pk(fmaxf(ta0.x, 0.f), fmaxf(ta0.x, 0.f));
            tB = pk(fmaxf(tb0.x, 0.f), fmaxf(tb0.x, 0.f));
            WE2_ROW2(tA, tB, 4*p + 0);
            tA = pk(fmaxf(ta0.y, 0.f), fmaxf(ta0.y, 0.f));
            tB = pk(fmaxf(tb0.y, 0.f), fmaxf(tb0.y, 0.f));
            WE2_ROW2(tA, tB, 4*p + 1);
            tA = pk(fmaxf(ta1.x, 0.f), fmaxf(ta1.x, 0.f));
            tB = pk(fmaxf(tb1.x, 0.f), fmaxf(tb1.x, 0.f));
            WE2_ROW2(tA, tB, 4*p + 2);
            tA = pk(fmaxf(ta1.y, 0.f), fmaxf(ta1.y, 0.f));
            tB = pk(fmaxf(tb1.y, 0.f), fmaxf(tb1.y, 0.f));
            WE2_ROW2(tA, tB, 4*p + 3);
        }

        // relu(m); w = m·Wx; magg += m (self edges predicated off).
        // No select on wa/wb needed: self edge has dx=dy=dz=0.
        bool selfa = (i1 == j);
        bool selfb = (i2 == j);
        u64 wacca = 0ull, waccb = 0ull;
        #pragma unroll
        for (int p = 0; p < 4; p++) {
            ulonglong2 wx = sWxv[p];
            float2 va0 = upk(m2a[2*p + 0]);
            float2 va1 = upk(m2a[2*p + 1]);
            float2 vb0 = upk(m2b[2*p + 0]);
            float2 vb1 = upk(m2b[2*p + 1]);
            u64 ka0 = pk(fmaxf(va0.x, 0.f), fmaxf(va0.y, 0.f));
            u64 ka1 = pk(fmaxf(va1.x, 0.f), fmaxf(va1.y, 0.f));
            u64 kb0 = pk(fmaxf(vb0.x, 0.f), fmaxf(vb0.y, 0.f));
            u64 kb1 = pk(fmaxf(vb1.x, 0.f), fmaxf(vb1.y, 0.f));
            f2fma_acc(wacca, ka0, wx.x);
            f2fma_acc(wacca, ka1, wx.y);
            f2fma_acc(waccb, kb0, wx.x);
            f2fma_acc(waccb, kb1, wx.y);
            if (!selfa) {
                magg2[2*p + 0] = f2add(magg2[2*p + 0], ka0);
                magg2[2*p + 1] = f2add(magg2[2*p + 1], ka1);
            }
            if (!selfb) {
                magg2[2*p + 0] = f2add(magg2[2*p + 0], kb0);
                magg2[2*p + 1] = f2add(magg2[2*p + 1], kb1);
            }
        }
        float2 wva = upk(wacca);
        float2 wvb = upk(waccb);
        float wa = wva.x + wva.y;
        float wb = wvb.x + wvb.y;
        ax = fmaf(dx1, wa, fmaf(dx2, wb, ax));
        ay = fmaf(dy1, wa, fmaf(dy2, wb, ay));
        az = fmaf(dz1, wa, fmaf(dz2, wb, az));
    }

    // warp butterfly reductions
    #pragma unroll
    for (int q = 0; q < 8; q++) {
        #pragma unroll
        for (int off = 16; off; off >>= 1)
            magg2[q] = f2add(magg2[q], __shfl_xor_sync(0xffffffffu, magg2[q], off));
    }
    #pragma unroll
    for (int off = 16; off; off >>= 1) {
        ax += __shfl_xor_sync(0xffffffffu, ax, off);
        ay += __shfl_xor_sync(0xffffffffu, ay, off);
        az += __shfl_xor_sync(0xffffffffu, az, off);
    }

    if (lane == 0) {
        float hv = g_hv[pc][node];
        const float inv = 1.f / (NN - 1);
        float ox = xj.x + ax*inv + vs[node*3 + 0]*hv;
        float oy = xj.y + ay*inv + vs[node*3 + 1]*hv;
        float oz = xj.z + az*inv + vs[node*3 + 2]*hv;
        if (last) {
            out[node*3 + 0] = ox;
            out[node*3 + 1] = oy;
            out[node*3 + 2] = oz;
        } else {
            g_x[nxt][node] = make_float4(ox, oy, oz, 0.f);
        }
    }

    if (!last) {   // uniform branch: syncthreads legal
        // stage next-layer node-precompute weights in shared (reuse sA2 region)
        float* sW = (float*)sA2;   // [0:256) We1A, [256:512) We1B, [512:768) Wh1A, [768:784) W_v
        int l1 = l + 1;
        __syncthreads();           // all sA2 reads done
        {
            const float* we1n = We1 + l1*(2*NF+1)*NF;
            const float* wh1n = Wh1 + l1*(2*NF)*NF;
            for (int idx = tid; idx < 512; idx += WPB*32) sW[idx]       = we1n[idx];
            for (int idx = tid; idx < 256; idx += WPB*32) sW[512 + idx] = wh1n[idx];
            if (tid < NF) sW[768 + tid] = W_v[l1*NF + tid];
        }

        // h update (uses sWh1b, separate buffer, still valid)
        float maggv[NF];
        #pragma unroll
        for (int q = 0; q < 8; q++) {
            float2 v = upk(magg2[q]);
            maggv[2*q] = v.x; maggv[2*q+1] = v.y;
        }
        if (lane < NF) {
            float g = g_hWh[pc][node*NF + lane];
            #pragma unroll
            for (int f = 0; f < NF; f++) g = fmaf(maggv[f], sWh1b[f*NF + lane], g);
            float hn = g_h[cur][node*NF + lane] + (g > 0.f ? g : 0.f);
            g_h[nxt][node*NF + lane] = hn;
            sHn[warp*NF + lane] = hn;
        }
        __syncthreads();           // weights staged + sHn visible

        // fused next-layer node-side precompute -> buffer pn (no reader this launch)
        if (lane < NF) {
            float a = 0.f, bb = 0.f, hw = 0.f;
            #pragma unroll
            for (int f = 0; f < NF; f++) {
                float hf = sHn[warp*NF + f];
                a  = fmaf(hf, sW[f*NF + lane],        a);
                bb = fmaf(hf, sW[256 + f*NF + lane],  bb);
                hw = fmaf(hf, sW[512 + f*NF + lane],  hw);
            }
            ((float*)g_A2[pn])[node*NF + lane]   = a;
            ((float*)g_Bjb2[pn])[node*NF + lane] = bb + be1[l1*NF + lane];
            g_hWh[pn][node*NF + lane] = hw + bh1[l1*NF + lane];
        } else if (lane == NF) {
            float hv = 0.f;
            #pragma unroll
            for (int f = 0; f < NF; f++) hv = fmaf(sHn[warp*NF + f], sW[768 + f], hv);
            g_hv[pn][node] = hv;
        }
    }
}

extern "C" void kernel_launch(void* const* d_in, const int* in_sizes, int n_in,
                              void* d_out, int out_size) {
    const float* xs      = (const float*)d_in[0];
    const float* vs      = (const float*)d_in[1];
    const float* charges = (const float*)d_in[2];
    const float* W_in    = (const float*)d_in[3];
    const float* b_in    = (const float*)d_in[4];
    const float* W_v     = (const float*)d_in[5];
    const float* We1     = (const float*)d_in[6];
    const float* be1     = (const float*)d_in[7];
    const float* We2     = (const float*)d_in[8];
    const float* be2     = (const float*)d_in[9];
    const float* Wx      = (const float*)d_in[10];
    const float* Wh1     = (const float*)d_in[11];
    const float* bh1     = (const float*)d_in[12];
    float* out = (float*)d_out;

    init_kernel<<<(NODES*NF + 255)/256, 256>>>(xs, charges, W_in, b_in,
                                               W_v, We1, be1, Wh1, bh1);
    int cur = 0;
    for (int l = 0; l < NL; l++) {
        int nxt = cur ^ 1;
        edge_kernel<<<BB*(NN/WPB), WPB*32>>>(l, cur, nxt, (l == NL-1) ? 1 : 0,
                                             We1, be1, We2, be2, Wx, Wh1, bh1, W_v,
                                             vs, out);
        cur = nxt;
    }
}

// round 16
// speedup vs baseline: 1.0032x; 1.0032x over previous
#include <cuda_runtime.h>

typedef unsigned long long u64;

#define BB 32
#define NN 256
#define NF 16
#define NL 3
#define NODES (BB*NN)
#define WPB 4   // warps (dst nodes) per block

// ping-pong state; precomputed node terms double-buffered by layer parity
__device__ float4 g_x[2][NODES];
__device__ float  g_h[2][NODES*NF];
__device__ u64    g_A2[2][NODES*(NF/2)];    // packed pairs: h_i @ We1[0:NF]
__device__ u64    g_Bjb2[2][NODES*(NF/2)];  // packed pairs: h_j @ We1[NF:2NF] + be1
__device__ float  g_hWh[2][NODES*NF];       // h_j @ Wh1[0:NF] + bh1
__device__ float  g_hv[2][NODES];           // h_j @ W_v

// ---- packed fp32x2 helpers (sm_103a FFMA2 path, PTX-only) ----
__device__ __forceinline__ u64 pk(float lo, float hi) {
    u64 r; asm("mov.b64 %0, {%1,%2};" : "=l"(r) : "f"(lo), "f"(hi)); return r;
}
__device__ __forceinline__ float2 upk(u64 v) {
    float2 r; asm("mov.b64 {%0,%1}, %2;" : "=f"(r.x), "=f"(r.y) : "l"(v)); return r;
}
__device__ __forceinline__ void f2fma_acc(u64& d, u64 a, u64 b) {
    asm("fma.rn.f32x2 %0, %1, %2, %0;" : "+l"(d) : "l"(a), "l"(b));
}
__device__ __forceinline__ u64 f2fma(u64 a, u64 b, u64 c) {
    u64 d; asm("fma.rn.f32x2 %0, %1, %2, %3;" : "=l"(d) : "l"(a), "l"(b), "l"(c)); return d;
}
__device__ __forceinline__ u64 f2add(u64 a, u64 b) {
    u64 d; asm("add.rn.f32x2 %0, %1, %2;" : "=l"(d) : "l"(a), "l"(b)); return d;
}

// init: node features h from charges, plus layer-0 node-side precompute (buffer 0)
__global__ void init_kernel(const float* __restrict__ xs,
                            const float* __restrict__ charges,
                            const float* __restrict__ W_in,
                            const float* __restrict__ b_in,
                            const float* __restrict__ W_v,
                            const float* __restrict__ We1,
                            const float* __restrict__ be1,
                            const float* __restrict__ Wh1,
                            const float* __restrict__ bh1) {
    int gid = blockIdx.x * blockDim.x + threadIdx.x;
    int node = gid >> 4;
    int k = gid & 15;
    if (node >= NODES) return;
    float c = charges[node];
    float h[NF];
    #pragma unroll
    for (int f = 0; f < NF; f++) {
        float v = fmaf(c, W_in[f], b_in[f]);
        h[f] = v > 0.f ? v : 0.f;
    }
    g_h[0][node*NF + k] = h[k];
    float a = 0.f, bb = 0.f, hw = 0.f;
    #pragma unroll
    for (int f = 0; f < NF; f++) {
        a  = fmaf(h[f], We1[f*NF + k],      a);
        bb = fmaf(h[f], We1[(NF+f)*NF + k], bb);
        hw = fmaf(h[f], Wh1[f*NF + k],      hw);
    }
    ((float*)g_A2[0])[node*NF + k]   = a;
    ((float*)g_Bjb2[0])[node*NF + k] = bb + be1[k];
    g_hWh[0][node*NF + k] = hw + bh1[k];
    if (k == 0) {
        float hv = 0.f;
        #pragma unroll
        for (int f = 0; f < NF; f++) hv = fmaf(h[f], W_v[f], hv);
        g_hv[0][node] = hv;
        float4 x;
        x.x = xs[node*3 + 0]; x.y = xs[node*3 + 1]; x.z = xs[node*3 + 2]; x.w = 0.f;
        g_x[0][node] = x;
    }
}

// one We2 row pass applied to TWO edges: weights loaded once, two FFMA2 streams
#define WE2_ROW2(TA, TB, F)                                          \
    do {                                                             \
        ulonglong2 wa = sWe2v[(F)*4 + 0];                            \
        ulonglong2 wb = sWe2v[(F)*4 + 1];                            \
        ulonglong2 wc = sWe2v[(F)*4 + 2];                            \
        ulonglong2 wd = sWe2v[(F)*4 + 3];                            \
        f2fma_acc(m2a[0], TA, wa.x); f2fma_acc(m2b[0], TB, wa.x);    \
        f2fma_acc(m2a[1], TA, wa.y); f2fma_acc(m2b[1], TB, wa.y);    \
        f2fma_acc(m2a[2], TA, wb.x); f2fma_acc(m2b[2], TB, wb.x);    \
        f2fma_acc(m2a[3], TA, wb.y); f2fma_acc(m2b[3], TB, wb.y);    \
        f2fma_acc(m2a[4], TA, wc.x); f2fma_acc(m2b[4], TB, wc.x);    \
        f2fma_acc(m2a[5], TA, wc.y); f2fma_acc(m2b[5], TB, wc.y);    \
        f2fma_acc(m2a[6], TA, wd.x); f2fma_acc(m2b[6], TB, wd.x);    \
        f2fma_acc(m2a[7], TA, wd.y); f2fma_acc(m2b[7], TB, wd.y);    \
    } while (0)

// min_blocks 6: caps regs at ~85 -> 6 blocks/SM (24 warps, 6/SMSP).
// R14 proved the load batching is elastic (96 regs, zero spills at cap 102);
// accumulator floor is 48 regs, so 85 leaves ~4-deep LDS batches spill-free.
__global__ void __launch_bounds__(WPB*32, 6)
edge_kernel(int l, int cur, int nxt, int last,
            const float* __restrict__ We1,
            const float* __restrict__ be1,
            const float* __restrict__ We2,
            const float* __restrict__ be2,
            const float* __restrict__ Wx,
            const float* __restrict__ Wh1,
            const float* __restrict__ bh1,
            const float* __restrict__ W_v,
            const float* __restrict__ vs,
            float* __restrict__ out) {
    __shared__ ulonglong2 sA2[4*NN];      // [p*NN + i] = (A pairs 2p, 2p+1); reused in epilogue
    __shared__ float4     sX[NN];
    __shared__ ulonglong2 sWe2v[NF*4];    // row f at [f*4..f*4+3]
    __shared__ ulonglong2 sBe2[4];        // be2[l] as 8 packed pairs
    __shared__ ulonglong2 sWxv[4];        // Wx[l]  as 8 packed pairs
    __shared__ ulonglong2 sWr2[4];        // We1 r2-row as 8 packed pairs
    __shared__ ulonglong2 sBjbW[WPB*4];   // per-warp Bjb pairs
    __shared__ float      sWh1b[NF*NF];   // Wh1 m_agg half [f][k]
    __shared__ float      sHn[WPB*NF];

    int tid  = threadIdx.x;
    int lane = tid & 31;
    int warp = tid >> 5;
    int b     = blockIdx.x >> 6;          // NN/WPB = 64 blocks per batch
    int jbase = (blockIdx.x & 63) * WPB;
    int nbase = b * NN;

    int pc = l & 1;        // precompute buffer for this layer
    int pn = pc ^ 1;       // precompute buffer for next layer

    int j = jbase + warp;
    int node = nbase + j;

    // cooperative tile loads
    for (int idx = tid; idx < NN*4; idx += WPB*32) {
        int i = idx >> 2, p = idx & 3;
        sA2[p*NN + i] = ((const ulonglong2*)g_A2[pc])[(nbase + i)*4 + p];
    }
    for (int i = tid; i < NN; i += WPB*32) sX[i] = g_x[cur][nbase + i];
    if (tid < NF*4) sWe2v[tid] = ((const ulonglong2*)We2)[l*(NF*NF/4) + tid];
    if (tid >= 64 && tid < 68) sBe2[tid-64] = ((const ulonglong2*)be2)[l*4 + (tid-64)];
    if (tid >= 68 && tid < 72) sWxv[tid-68] = ((const ulonglong2*)Wx)[l*4 + (tid-68)];
    if (tid >= 72 && tid < 76)
        sWr2[tid-72] = ((const ulonglong2*)We1)[(l*(2*NF+1)*NF + 2*NF*NF)/4 + (tid-72)];
    if (lane < 4) sBjbW[warp*4 + lane] = ((const ulonglong2*)g_Bjb2[pc])[node*4 + lane];
    for (int idx = tid; idx < NF*NF; idx += WPB*32) {
        int f = idx >> 4, k = idx & 15;
        sWh1b[idx] = Wh1[l*(2*NF)*NF + (NF + f)*NF + k];
    }
    __syncthreads();

    float4 xj = sX[j];

    u64 magg2[8];
    #pragma unroll
    for (int q = 0; q < 8; q++) magg2[q] = 0ull;
    float ax = 0.f, ay = 0.f, az = 0.f;

    // Two edges per lane per iteration: i1 = it*64+lane, i2 = i1+32.
    // Weights loaded once per chunk feed BOTH m2a and m2b streams.
    #pragma unroll 1
    for (int it = 0; it < NN/64; it++) {
        int i1 = it*64 + lane;
        int i2 = i1 + 32;
        float4 xi1 = sX[i1];
        float4 xi2 = sX[i2];
        float dx1 = xj.x - xi1.x, dy1 = xj.y - xi1.y, dz1 = xj.z - xi1.z;
        float dx2 = xj.x - xi2.x, dy2 = xj.y - xi2.y, dz2 = xj.z - xi2.z;
        float r2a = fmaf(dx1, dx1, fmaf(dy1, dy1, dz1*dz1));
        float r2b = fmaf(dx2, dx2, fmaf(dy2, dy2, dz2*dz2));
        u64 r22a = pk(r2a, r2a);
        u64 r22b = pk(r2b, r2b);

        u64 m2a[8], m2b[8];
        {
            ulonglong2 b0 = sBe2[0], b1 = sBe2[1], b2 = sBe2[2], b3 = sBe2[3];
            m2a[0] = b0.x; m2a[1] = b0.y; m2a[2] = b1.x; m2a[3] = b1.y;
            m2a[4] = b2.x; m2a[5] = b2.y; m2a[6] = b3.x; m2a[7] = b3.y;
            m2b[0] = b0.x; m2b[1] = b0.y; m2b[2] = b1.x; m2b[3] = b1.y;
            m2b[4] = b2.x; m2b[5] = b2.y; m2b[6] = b3.x; m2b[7] = b3.y;
        }

        // unroll 1: bounds the LDS batch per chunk (spill guard, see R10->R11)
        #pragma unroll 1
        for (int p = 0; p < 4; p++) {
            ulonglong2 a2a = sA2[p*NN + i1];
            ulonglong2 a2b = sA2[p*NN + i2];
            ulonglong2 bj  = sBjbW[warp*4 + p];
            ulonglong2 wr  = sWr2[p];
            float2 ta0 = upk(f2fma(r22a, wr.x, f2add(a2a.x, bj.x)));
            float2 ta1 = upk(f2fma(r22a, wr.y, f2add(a2a.y, bj.y)));
            float2 tb0 = upk(f2fma(r22b, wr.x, f2add(a2b.x, bj.x)));
            float2 tb1 = upk(f2fma(r22b, wr.y, f2add(a2b.y, bj.y)));
            u64 tA, tB;
            tA = pk(fmaxf(ta0.x, 0.f), fmaxf(ta0.x, 0.f));
            tB = pk(fmaxf(tb0.x, 0.f), fmaxf(tb0.x, 0.f));
            WE2_ROW2(tA, tB, 4*p + 0);
            tA = pk(fmaxf(ta0.y, 0.f), fmaxf(ta0.y, 0.f));
            tB = pk(fmaxf(tb0.y, 0.f), fmaxf(tb0.y, 0.f));
            WE2_ROW2(tA, tB, 4*p + 1);
            tA = pk(fmaxf(ta1.x, 0.f), fmaxf(ta1.x, 0.f));
            tB = pk(fmaxf(tb1.x, 0.f), fmaxf(tb1.x, 0.f));
            WE2_ROW2(tA, tB, 4*p + 2);
            tA = pk(fmaxf(ta1.y, 0.f), fmaxf(ta1.y, 0.f));
            tB = pk(fmaxf(tb1.y, 0.f), fmaxf(tb1.y, 0.f));
            WE2_ROW2(tA, tB, 4*p + 3);
        }

        // relu(m); w = m·Wx; magg += m (self edges predicated off).
        // No select on wa/wb needed: self edge has dx=dy=dz=0.
        bool selfa = (i1 == j);
        bool selfb = (i2 == j);
        u64 wacca = 0ull, waccb = 0ull;
        #pragma unroll
        for (int p = 0; p < 4; p++) {
            ulonglong2 wx = sWxv[p];
            float2 va0 = upk(m2a[2*p + 0]);
            float2 va1 = upk(m2a[2*p + 1]);
            float2 vb0 = upk(m2b[2*p + 0]);
            float2 vb1 = upk(m2b[2*p + 1]);
            u64 ka0 = pk(fmaxf(va0.x, 0.f), fmaxf(va0.y, 0.f));
            u64 ka1 = pk(fmaxf(va1.x, 0.f), fmaxf(va1.y, 0.f));
            u64 kb0 = pk(fmaxf(vb0.x, 0.f), fmaxf(vb0.y, 0.f));
            u64 kb1 = pk(fmaxf(vb1.x, 0.f), fmaxf(vb1.y, 0.f));
            f2fma_acc(wacca, ka0, wx.x);
            f2fma_acc(wacca, ka1, wx.y);
            f2fma_acc(waccb, kb0, wx.x);
            f2fma_acc(waccb, kb1, wx.y);
            if (!selfa) {
                magg2[2*p + 0] = f2add(magg2[2*p + 0], ka0);
                magg2[2*p + 1] = f2add(magg2[2*p + 1], ka1);
            }
            if (!selfb) {
                magg2[2*p + 0] = f2add(magg2[2*p + 0], kb0);
                magg2[2*p + 1] = f2add(magg2[2*p + 1], kb1);
            }
        }
        float2 wva = upk(wacca);
        float2 wvb = upk(waccb);
        float wa = wva.x + wva.y;
        float wb = wvb.x + wvb.y;
        ax = fmaf(dx1, wa, fmaf(dx2, wb, ax));
        ay = fmaf(dy1, wa, fmaf(dy2, wb, ay));
        az = fmaf(dz1, wa, fmaf(dz2, wb, az));
    }

    // warp butterfly reductions
    #pragma unroll
    for (int q = 0; q < 8; q++) {
        #pragma unroll
        for (int off = 16; off; off >>= 1)
            magg2[q] = f2add(magg2[q], __shfl_xor_sync(0xffffffffu, magg2[q], off));
    }
    #pragma unroll
    for (int off = 16; off; off >>= 1) {
        ax += __shfl_xor_sync(0xffffffffu, ax, off);
        ay += __shfl_xor_sync(0xffffffffu, ay, off);
        az += __shfl_xor_sync(0xffffffffu, az, off);
    }

    if (lane == 0) {
        float hv = g_hv[pc][node];
        const float inv = 1.f / (NN - 1);
        float ox = xj.x + ax*inv + vs[node*3 + 0]*hv;
        float oy = xj.y + ay*inv + vs[node*3 + 1]*hv;
        float oz = xj.z + az*inv + vs[node*3 + 2]*hv;
        if (last) {
            out[node*3 + 0] = ox;
            out[node*3 + 1] = oy;
            out[node*3 + 2] = oz;
        } else {
            g_x[nxt][node] = make_float4(ox, oy, oz, 0.f);
        }
    }

    if (!last) {   // uniform branch: syncthreads legal
        // stage next-layer node-precompute weights in shared (reuse sA2 region)
        float* sW = (float*)sA2;   // [0:256) We1A, [256:512) We1B, [512:768) Wh1A, [768:784) W_v
        int l1 = l + 1;
        __syncthreads();           // all sA2 reads done
        {
            const float* we1n = We1 + l1*(2*NF+1)*NF;
            const float* wh1n = Wh1 + l1*(2*NF)*NF;
            for (int idx = tid; idx < 512; idx += WPB*32) sW[idx]       = we1n[idx];
            for (int idx = tid; idx < 256; idx += WPB*32) sW[512 + idx] = wh1n[idx];
            if (tid < NF) sW[768 + tid] = W_v[l1*NF + tid];
        }

        // h update (uses sWh1b, separate buffer, still valid)
        float maggv[NF];
        #pragma unroll
        for (int q = 0; q < 8; q++) {
            float2 v = upk(magg2[q]);
            maggv[2*q] = v.x; maggv[2*q+1] = v.y;
        }
        if (lane < NF) {
            float g = g_hWh[pc][node*NF + lane];
            #pragma unroll
            for (int f = 0; f < NF; f++) g = fmaf(maggv[f], sWh1b[f*NF + lane], g);
            float hn = g_h[cur][node*NF + lane] + (g > 0.f ? g : 0.f);
            g_h[nxt][node*NF + lane] = hn;
            sHn[warp*NF + lane] = hn;
        }
        __syncthreads();           // weights staged + sHn visible

        // fused next-layer node-side precompute -> buffer pn (no reader this launch)
        if (lane < NF) {
            float a = 0.f, bb = 0.f, hw = 0.f;
            #pragma unroll
            for (int f = 0; f < NF; f++) {
                float hf = sHn[warp*NF + f];
                a  = fmaf(hf, sW[f*NF + lane],        a);
                bb = fmaf(hf, sW[256 + f*NF + lane],  bb);
                hw = fmaf(hf, sW[512 + f*NF + lane],  hw);
            }
            ((float*)g_A2[pn])[node*NF + lane]   = a;
            ((float*)g_Bjb2[pn])[node*NF + lane] = bb + be1[l1*NF + lane];
            g_hWh[pn][node*NF + lane] = hw + bh1[l1*NF + lane];
        } else if (lane == NF) {
            float hv = 0.f;
            #pragma unroll
            for (int f = 0; f < NF; f++) hv = fmaf(sHn[warp*NF + f], sW[768 + f], hv);
            g_hv[pn][node] = hv;
        }
    }
}

extern "C" void kernel_launch(void* const* d_in, const int* in_sizes, int n_in,
                              void* d_out, int out_size) {
    const float* xs      = (const float*)d_in[0];
    const float* vs      = (const float*)d_in[1];
    const float* charges = (const float*)d_in[2];
    const float* W_in    = (const float*)d_in[3];
    const float* b_in    = (const float*)d_in[4];
    const float* W_v     = (const float*)d_in[5];
    const float* We1     = (const float*)d_in[6];
    const float* be1     = (const float*)d_in[7];
    const float* We2     = (const float*)d_in[8];
    const float* be2     = (const float*)d_in[9];
    const float* Wx      = (const float*)d_in[10];
    const float* Wh1     = (const float*)d_in[11];
    const float* bh1     = (const float*)d_in[12];
    float* out = (float*)d_out;

    init_kernel<<<(NODES*NF + 255)/256, 256>>>(xs, charges, W_in, b_in,
                                               W_v, We1, be1, Wh1, bh1);
    int cur = 0;
    for (int l = 0; l < NL; l++) {
        int nxt = cur ^ 1;
        edge_kernel<<<BB*(NN/WPB), WPB*32>>>(l, cur, nxt, (l == NL-1) ? 1 : 0,
                                             We1, be1, We2, be2, Wx, Wh1, bh1, W_v,
                                             vs, out);
        cur = nxt;
    }
}

// round 17
// speedup vs baseline: 1.2173x; 1.2134x over previous
#include <cuda_runtime.h>
#include <cstdint>

typedef unsigned long long u64;

#define BB 32
#define NN 256
#define NF 16
#define NL 3
#define NODES (BB*NN)
#define WPB 4
#define TPAD 72   // tbuf row stride words: (8*tig+g) mod 32 distinct -> conflict-free

__device__ float4 g_x[2][NODES];
__device__ float  g_h[2][NODES*NF];
__device__ u64    g_A2[2][NODES*(NF/2)];
__device__ u64    g_Bjb2[2][NODES*(NF/2)];
__device__ float  g_hWh[2][NODES*NF];
__device__ float  g_hv[2][NODES];

__device__ __forceinline__ u64 pk(float lo, float hi) {
    u64 r; asm("mov.b64 %0, {%1,%2};" : "=l"(r) : "f"(lo), "f"(hi)); return r;
}
__device__ __forceinline__ float2 upk(u64 v) {
    float2 r; asm("mov.b64 {%0,%1}, %2;" : "=f"(r.x), "=f"(r.y) : "l"(v)); return r;
}
__device__ __forceinline__ u64 f2fma(u64 a, u64 b, u64 c) {
    u64 d; asm("fma.rn.f32x2 %0, %1, %2, %3;" : "=l"(d) : "l"(a), "l"(b), "l"(c)); return d;
}
__device__ __forceinline__ u64 f2add(u64 a, u64 b) {
    u64 d; asm("add.rn.f32x2 %0, %1, %2;" : "=l"(d) : "l"(a), "l"(b)); return d;
}
__device__ __forceinline__ uint32_t tf32c(float x) {
    uint32_t r; asm("cvt.rna.tf32.f32 %0, %1;" : "=r"(r) : "f"(x)); return r;
}
__device__ __forceinline__ void mma8(float& d0, float& d1, float& d2, float& d3,
                                     uint32_t a0, uint32_t a1, uint32_t a2, uint32_t a3,
                                     uint32_t b0, uint32_t b1) {
    asm("mma.sync.aligned.m16n8k8.row.col.f32.tf32.tf32.f32 "
        "{%0,%1,%2,%3}, {%4,%5,%6,%7}, {%8,%9}, {%0,%1,%2,%3};"
        : "+f"(d0), "+f"(d1), "+f"(d2), "+f"(d3)
        : "r"(a0), "r"(a1), "r"(a2), "r"(a3), "r"(b0), "r"(b1));
}

__global__ void init_kernel(const float* __restrict__ xs,
                            const float* __restrict__ charges,
                            const float* __restrict__ W_in,
                            const float* __restrict__ b_in,
                            const float* __restrict__ W_v,
                            const float* __restrict__ We1,
                            const float* __restrict__ be1,
                            const float* __restrict__ Wh1,
                            const float* __restrict__ bh1) {
    int gid = blockIdx.x * blockDim.x + threadIdx.x;
    int node = gid >> 4;
    int k = gid & 15;
    if (node >= NODES) return;
    float c = charges[node];
    float h[NF];
    #pragma unroll
    for (int f = 0; f < NF; f++) {
        float v = fmaf(c, W_in[f], b_in[f]);
        h[f] = v > 0.f ? v : 0.f;
    }
    g_h[0][node*NF + k] = h[k];
    float a = 0.f, bb = 0.f, hw = 0.f;
    #pragma unroll
    for (int f = 0; f < NF; f++) {
        a  = fmaf(h[f], We1[f*NF + k],      a);
        bb = fmaf(h[f], We1[(NF+f)*NF + k], bb);
        hw = fmaf(h[f], Wh1[f*NF + k],      hw);
    }
    ((float*)g_A2[0])[node*NF + k]   = a;
    ((float*)g_Bjb2[0])[node*NF + k] = bb + be1[k];
    g_hWh[0][node*NF + k] = hw + bh1[k];
    if (k == 0) {
        float hv = 0.f;
        #pragma unroll
        for (int f = 0; f < NF; f++) hv = fmaf(h[f], W_v[f], hv);
        g_hv[0][node] = hv;
        float4 x;
        x.x = xs[node*3 + 0]; x.y = xs[node*3 + 1]; x.z = xs[node*3 + 2]; x.w = 0.f;
        g_x[0][node] = x;
    }
}

__global__ void __launch_bounds__(WPB*32, 5)
edge_kernel(int l, int cur, int nxt, int last,
            const float* __restrict__ We1,
            const float* __restrict__ be1,
            const float* __restrict__ We2,
            const float* __restrict__ be2,
            const float* __restrict__ Wx,
            const float* __restrict__ Wh1,
            const float* __restrict__ bh1,
            const float* __restrict__ W_v,
            const float* __restrict__ vs,
            float* __restrict__ out) {
    __shared__ ulonglong2 sA2[4*NN];
    __shared__ float4     sX[NN];
    __shared__ ulonglong2 sWr2[4];
    __shared__ ulonglong2 sBjbW[WPB*4];
    __shared__ float      sWh1b[NF*NF];
    __shared__ float      sHn[WPB*NF];
    __shared__ uint32_t   tbuf[WPB][16*TPAD];
    __shared__ float      wbuf[WPB][64];
    __shared__ float      sMagg[WPB][NF];

    int tid  = threadIdx.x;
    int lane = tid & 31;
    int warp = tid >> 5;
    int tig  = lane & 3;
    int g    = lane >> 2;
    int b     = blockIdx.x >> 6;
    int jbase = (blockIdx.x & 63) * WPB;
    int nbase = b * NN;

    int pc = l & 1, pn = pc ^ 1;
    int j = jbase + warp;
    int node = nbase + j;

    for (int idx = tid; idx < NN*4; idx += WPB*32) {
        int i = idx >> 2, p = idx & 3;
        sA2[p*NN + i] = ((const ulonglong2*)g_A2[pc])[(nbase + i)*4 + p];
    }
    for (int i = tid; i < NN; i += WPB*32) sX[i] = g_x[cur][nbase + i];
    if (tid < 4)
        sWr2[tid] = ((const ulonglong2*)We1)[(l*(2*NF+1)*NF + 2*NF*NF)/4 + tid];
    if (lane < 4) sBjbW[warp*4 + lane] = ((const ulonglong2*)g_Bjb2[pc])[node*4 + lane];
    for (int idx = tid; idx < NF*NF; idx += WPB*32) {
        int f = idx >> 4, k = idx & 15;
        sWh1b[idx] = Wh1[l*(2*NF)*NF + (NF + f)*NF + k];
    }
    __syncthreads();

    // fragment constants (per thread, L1-cached LDG)
    const float* we2l = We2 + l*NF*NF;
    uint32_t Bf00a = tf32c(we2l[(tig)*NF + g]);
    uint32_t Bf00b = tf32c(we2l[(tig+4)*NF + g]);
    uint32_t Bf01a = tf32c(we2l[(tig)*NF + 8 + g]);
    uint32_t Bf01b = tf32c(we2l[(tig+4)*NF + 8 + g]);
    uint32_t Bf10a = tf32c(we2l[(8+tig)*NF + g]);
    uint32_t Bf10b = tf32c(we2l[(12+tig)*NF + g]);
    uint32_t Bf11a = tf32c(we2l[(8+tig)*NF + 8 + g]);
    uint32_t Bf11b = tf32c(we2l[(12+tig)*NF + 8 + g]);
    float bc00 = be2[l*NF + 2*tig],     bc01 = be2[l*NF + 2*tig + 1];
    float bc10 = be2[l*NF + 8 + 2*tig], bc11 = be2[l*NF + 9 + 2*tig];
    float wx00 = Wx[l*NF + 2*tig],      wx01 = Wx[l*NF + 2*tig + 1];
    float wx10 = Wx[l*NF + 8 + 2*tig],  wx11 = Wx[l*NF + 9 + 2*tig];

    float4 xj = sX[j];
    float ax = 0.f, ay = 0.f, az = 0.f;
    float MGA = 0.f, MGB = 0.f, MGC = 0.f, MGD = 0.f;  // cols 2tig,2tig+1,8+2tig,9+2tig

    uint32_t* tb = tbuf[warp];
    float*    wb = wbuf[warp];

    #pragma unroll 1
    for (int it = 0; it < 4; it++) {
        int i1 = it*64 + lane;
        int i2 = i1 + 32;
        float4 xi1 = sX[i1];
        float4 xi2 = sX[i2];
        float dx1 = xj.x - xi1.x, dy1 = xj.y - xi1.y, dz1 = xj.z - xi1.z;
        float dx2 = xj.x - xi2.x, dy2 = xj.y - xi2.y, dz2 = xj.z - xi2.z;
        float r2a = fmaf(dx1, dx1, fmaf(dy1, dy1, dz1*dz1));
        float r2b = fmaf(dx2, dx2, fmaf(dy2, dy2, dz2*dz2));
        u64 r22a = pk(r2a, r2a);
        u64 r22b = pk(r2b, r2b);

        // t-phase: t = relu(A_i + Bjb_j + r2*wr) -> tf32, tbuf[f][edge]
        #pragma unroll 1
        for (int p = 0; p < 4; p++) {
            ulonglong2 aa = sA2[p*NN + i1];
            ulonglong2 ab = sA2[p*NN + i2];
            ulonglong2 bj = sBjbW[warp*4 + p];
            ulonglong2 wr = sWr2[p];
            float2 A0 = upk(f2fma(r22a, wr.x, f2add(aa.x, bj.x)));
            float2 A1 = upk(f2fma(r22a, wr.y, f2add(aa.y, bj.y)));
            float2 B0 = upk(f2fma(r22b, wr.x, f2add(ab.x, bj.x)));
            float2 B1 = upk(f2fma(r22b, wr.y, f2add(ab.y, bj.y)));
            tb[(4*p+0)*TPAD + lane]      = tf32c(fmaxf(A0.x, 0.f));
            tb[(4*p+1)*TPAD + lane]      = tf32c(fmaxf(A0.y, 0.f));
            tb[(4*p+2)*TPAD + lane]      = tf32c(fmaxf(A1.x, 0.f));
            tb[(4*p+3)*TPAD + lane]      = tf32c(fmaxf(A1.y, 0.f));
            tb[(4*p+0)*TPAD + lane + 32] = tf32c(fmaxf(B0.x, 0.f));
            tb[(4*p+1)*TPAD + lane + 32] = tf32c(fmaxf(B0.y, 0.f));
            tb[(4*p+2)*TPAD + lane + 32] = tf32c(fmaxf(B1.x, 0.f));
            tb[(4*p+3)*TPAD + lane + 32] = tf32c(fmaxf(B1.y, 0.f));
        }
        __syncwarp();

        // m = t @ We2 + be2 on tensor pipe; relu/magg/w on D fragments
        #pragma unroll 1
        for (int m = 0; m < 4; m++) {
            int rbase = m*16 + g;
            float d00 = bc00, d01 = bc01, d02 = bc00, d03 = bc01;
            float d10 = bc10, d11 = bc11, d12 = bc10, d13 = bc11;
            uint32_t a0 = tb[tig*TPAD + rbase];
            uint32_t a1 = tb[tig*TPAD + rbase + 8];
            uint32_t a2 = tb[(tig+4)*TPAD + rbase];
            uint32_t a3 = tb[(tig+4)*TPAD + rbase + 8];
            mma8(d00, d01, d02, d03, a0, a1, a2, a3, Bf00a, Bf00b);
            mma8(d10, d11, d12, d13, a0, a1, a2, a3, Bf01a, Bf01b);
            uint32_t c0 = tb[(8+tig)*TPAD + rbase];
            uint32_t c1 = tb[(8+tig)*TPAD + rbase + 8];
            uint32_t c2 = tb[(12+tig)*TPAD + rbase];
            uint32_t c3 = tb[(12+tig)*TPAD + rbase + 8];
            mma8(d00, d01, d02, d03, c0, c1, c2, c3, Bf10a, Bf10b);
            mma8(d10, d11, d12, d13, c0, c1, c2, c3, Bf11a, Bf11b);

            float r00 = fmaxf(d00, 0.f), r01 = fmaxf(d01, 0.f);
            float r02 = fmaxf(d02, 0.f), r03 = fmaxf(d03, 0.f);
            float r10 = fmaxf(d10, 0.f), r11 = fmaxf(d11, 0.f);
            float r12 = fmaxf(d12, 0.f), r13 = fmaxf(d13, 0.f);
            int i_row0 = it*64 + rbase;          // row0 = rbase, row1 = rbase+8
            if (i_row0 != j)     { MGA += r00; MGB += r01; MGC += r10; MGD += r11; }
            if (i_row0 + 8 != j) { MGA += r02; MGB += r03; MGC += r12; MGD += r13; }
            float pw0 = fmaf(r00, wx00, fmaf(r01, wx01, fmaf(r10, wx10, r11*wx11)));
            float pw1 = fmaf(r02, wx00, fmaf(r03, wx01, fmaf(r12, wx10, r13*wx11)));
            pw0 += __shfl_xor_sync(0xffffffffu, pw0, 1);
            pw0 += __shfl_xor_sync(0xffffffffu, pw0, 2);
            pw1 += __shfl_xor_sync(0xffffffffu, pw1, 1);
            pw1 += __shfl_xor_sync(0xffffffffu, pw1, 2);
            if (tig == 0) { wb[rbase] = pw0; wb[rbase + 8] = pw1; }
        }
        __syncwarp();

        float wA = wb[lane];
        float wB = wb[lane + 32];
        ax = fmaf(dx1, wA, fmaf(dx2, wB, ax));   // self edge: d=0, harmless
        ay = fmaf(dy1, wA, fmaf(dy2, wB, ay));
        az = fmaf(dz1, wA, fmaf(dz2, wB, az));
        __syncwarp();
    }

    // ax/ay/az full-warp butterfly
    #pragma unroll
    for (int off = 16; off; off >>= 1) {
        ax += __shfl_xor_sync(0xffffffffu, ax, off);
        ay += __shfl_xor_sync(0xffffffffu, ay, off);
        az += __shfl_xor_sync(0xffffffffu, az, off);
    }

    if (lane == 0) {
        float hv = g_hv[pc][node];
        const float inv = 1.f / (NN - 1);
        float ox = xj.x + ax*inv + vs[node*3 + 0]*hv;
        float oy = xj.y + ay*inv + vs[node*3 + 1]*hv;
        float oz = xj.z + az*inv + vs[node*3 + 2]*hv;
        if (last) {
            out[node*3 + 0] = ox;
            out[node*3 + 1] = oy;
            out[node*3 + 2] = oz;
        } else {
            g_x[nxt][node] = make_float4(ox, oy, oz, 0.f);
        }
    }

    if (!last) {
        // magg reduce across g (lanes stride 4), publish 16 values
        #pragma unroll
        for (int off = 4; off <= 16; off <<= 1) {
            MGA += __shfl_xor_sync(0xffffffffu, MGA, off);
            MGB += __shfl_xor_sync(0xffffffffu, MGB, off);
            MGC += __shfl_xor_sync(0xffffffffu, MGC, off);
            MGD += __shfl_xor_sync(0xffffffffu, MGD, off);
        }
        if (lane < 4) {
            sMagg[warp][2*lane]     = MGA;
            sMagg[warp][2*lane + 1] = MGB;
            sMagg[warp][8 + 2*lane] = MGC;
            sMagg[warp][9 + 2*lane] = MGD;
        }
        __syncwarp();

        // stage next-layer node-precompute weights (reuse sA2)
        float* sW = (float*)sA2;
        int l1 = l + 1;
        __syncthreads();
        {
            const float* we1n = We1 + l1*(2*NF+1)*NF;
            const float* wh1n = Wh1 + l1*(2*NF)*NF;
            for (int idx = tid; idx < 512; idx += WPB*32) sW[idx]       = we1n[idx];
            for (int idx = tid; idx < 256; idx += WPB*32) sW[512 + idx] = wh1n[idx];
            if (tid < NF) sW[768 + tid] = W_v[l1*NF + tid];
        }

        if (lane < NF) {
            float gg = g_hWh[pc][node*NF + lane];
            #pragma unroll
            for (int f = 0; f < NF; f++) gg = fmaf(sMagg[warp][f], sWh1b[f*NF + lane], gg);
            float hn = g_h[cur][node*NF + lane] + (gg > 0.f ? gg : 0.f);
            g_h[nxt][node*NF + lane] = hn;
            sHn[warp*NF + lane] = hn;
        }
        __syncthreads();

        if (lane < NF) {
            float a = 0.f, bb = 0.f, hw = 0.f;
            #pragma unroll
            for (int f = 0; f < NF; f++) {
                float hf = sHn[warp*NF + f];
                a  = fmaf(hf, sW[f*NF + lane],       a);
                bb = fmaf(hf, sW[256 + f*NF + lane], bb);
                hw = fmaf(hf, sW[512 + f*NF + lane], hw);
            }
            ((float*)g_A2[pn])[node*NF + lane]   = a;
            ((float*)g_Bjb2[pn])[node*NF + lane] = bb + be1[l1*NF + lane];
            g_hWh[pn][node*NF + lane] = hw + bh1[l1*NF + lane];
        } else if (lane == NF) {
            float hv = 0.f;
            #pragma unroll
            for (int f = 0; f < NF; f++) hv = fmaf(sHn[warp*NF + f], sW[768 + f], hv);
            g_hv[pn][node] = hv;
        }
    }
}

extern "C" void kernel_launch(void* const* d_in, const int* in_sizes, int n_in,
                              void* d_out, int out_size) {
    const float* xs      = (const float*)d_in[0];
    const float* vs      = (const float*)d_in[1];
    const float* charges = (const float*)d_in[2];
    const float* W_in    = (const float*)d_in[3];
    const float* b_in    = (const float*)d_in[4];
    const float* W_v     = (const float*)d_in[5];
    const float* We1     = (const float*)d_in[6];
    const float* be1     = (const float*)d_in[7];
    const float* We2     = (const float*)d_in[8];
    const float* be2     = (const float*)d_in[9];
    const float* Wx      = (const float*)d_in[10];
    const float* Wh1     = (const float*)d_in[11];
    const float* bh1     = (const float*)d_in[12];
    float* out = (float*)d_out;

    init_kernel<<<(NODES*NF + 255)/256, 256>>>(xs, charges, W_in, b_in,
                                               W_v, We1, be1, Wh1, bh1);
    int cur = 0;
    for (int l = 0; l < NL; l++) {
        int nxt = cur ^ 1;
        edge_kernel<<<BB*(NN/WPB), WPB*32>>>(l, cur, nxt, (l == NL-1) ? 1 : 0,
                                             We1, be1, We2, be2, Wx, Wh1, bh1, W_v,
                                             vs, out);
        cur = nxt;
    }
}